// round 13
// baseline (speedup 1.0000x reference)
#include <cuda_runtime.h>
#include <math.h>

#define FM_B 2
#define FM_C 256
#define FM_H 50
#define FM_W 50
#define FM_HW (FM_H * FM_W)      // 2500
#define POOL 7
#define NBINS (POOL * POOL)      // 49
#define R_ROIS 256
#define POS_F4 (FM_C / 4)        // 64 float4 per spatial position

// Channel-last scratch: [B, H, W, C] = 5.12 MB
__device__ float d_fm_t[FM_B * FM_HW * FM_C];
// Per-roi edge table: [r][0]=b, [1+ph]=hs, [8+ph]=he, [15+pw]=ws, [22+pw]=we
__device__ int d_edges[R_ROIS * 32];

// ---------------------------------------------------------------------------
// Kernel 1: transpose [B, C, HW] -> [B, HW, C], float4 both sides.
// Block (0,0,0) additionally decodes all 256 ROIs into d_edges.
// ---------------------------------------------------------------------------
__global__ void __launch_bounds__(256) transpose_kernel(
        const float* __restrict__ fm, const float* __restrict__ rois) {
    __shared__ float tile[32][33];
    int hw0 = blockIdx.x * 32;
    int c0  = blockIdx.y * 32;
    int b   = blockIdx.z;
    int tx = threadIdx.x;   // 0..7
    int ty = threadIdx.y;   // 0..31
    int tid = ty * 8 + tx;  // 0..255

    // --- piggybacked ROI decode: one thread per roi, once per grid ---
    if (blockIdx.x == 0 && blockIdx.y == 0 && blockIdx.z == 0) {
        int r = tid;
        const float* roi = rois + r * 5;
        int rb = (int)roi[0];
        int x1 = (int)rintf(roi[1]);
        int y1 = (int)rintf(roi[2]);
        int x2 = (int)rintf(roi[3]);
        int y2 = (int)rintf(roi[4]);
        int roi_w = max(x2 - x1 + 1, 1);
        int roi_h = max(y2 - y1 + 1, 1);
        // Replicate XLA fast-math: x/7 -> x * fl(1/7)  (0x3E124925)
        const float RCP7 = __uint_as_float(0x3E124925u);
        float bin_w = __fmul_rn((float)roi_w, RCP7);
        float bin_h = __fmul_rn((float)roi_h, RCP7);
        int* e = d_edges + r * 32;
        e[0] = rb;
        #pragma unroll
        for (int p = 0; p < POOL; ++p) {
            e[1 + p]  = min(max(y1 + (int)floorf(__fmul_rn((float)p,       bin_h)), 0), FM_H);
            e[8 + p]  = min(max(y1 + (int)ceilf (__fmul_rn((float)(p + 1), bin_h)), 0), FM_H);
            e[15 + p] = min(max(x1 + (int)floorf(__fmul_rn((float)p,       bin_w)), 0), FM_W);
            e[22 + p] = min(max(x1 + (int)ceilf (__fmul_rn((float)(p + 1), bin_w)), 0), FM_W);
        }
    }

    int hw = hw0 + tx * 4;
    const float* src = fm + ((size_t)b * FM_C + c0 + ty) * FM_HW + hw;
    if (hw + 3 < FM_HW) {
        float4 v = *reinterpret_cast<const float4*>(src);
        tile[ty][tx * 4 + 0] = v.x; tile[ty][tx * 4 + 1] = v.y;
        tile[ty][tx * 4 + 2] = v.z; tile[ty][tx * 4 + 3] = v.w;
    } else {
        #pragma unroll
        for (int k = 0; k < 4; ++k)
            if (hw + k < FM_HW) tile[ty][tx * 4 + k] = src[k];
    }
    __syncthreads();

    int hw2 = hw0 + ty;
    if (hw2 < FM_HW) {
        float4 v;
        v.x = tile[tx * 4 + 0][ty]; v.y = tile[tx * 4 + 1][ty];
        v.z = tile[tx * 4 + 2][ty]; v.w = tile[tx * 4 + 3][ty];
        *reinterpret_cast<float4*>(
            d_fm_t + ((size_t)b * FM_HW + hw2) * FM_C + c0 + tx * 4) = v;
    }
}

__device__ __forceinline__ float4 f4max(float4 a, float4 v) {
    a.x = fmaxf(a.x, v.x); a.y = fmaxf(a.y, v.y);
    a.z = fmaxf(a.z, v.z); a.w = fmaxf(a.w, v.w);
    return a;
}

// ---------------------------------------------------------------------------
// Kernel 2: block = (roi, ph strip, channel half), 224 threads = 7 warps.
// Warp wid owns bin pw = wid. Edges read from precomputed table (broadcast).
// Round-11 inner loop: always-4-loads steady state (clamped duplicates are
// cheaper than exposed latency — measured).
// ---------------------------------------------------------------------------
__global__ void __launch_bounds__(224) roi_pool_f4(
        float* __restrict__ out) {
    __shared__ float s_res[128 * POOL];   // [c_local][pw]

    int bid  = blockIdx.x;
    int half = bid & 1;
    int ph   = (bid >> 1) % POOL;
    int r    = bid / (2 * POOL);
    int tid  = threadIdx.x;
    int wid  = tid >> 5;       // 0..6 == pw
    int lane = tid & 31;

    const int* e = d_edges + r * 32;
    int b  = __ldg(e);
    int hs = __ldg(e + 1 + ph);
    int he = __ldg(e + 8 + ph);
    int ws = __ldg(e + 15 + wid);
    int we = __ldg(e + 22 + wid);
    int n  = we - ws;
    int pw = wid;

    const float4* base = reinterpret_cast<const float4*>(d_fm_t)
                       + (size_t)b * FM_HW * POS_F4 + half * 32 + lane;

    const float4 NEG = make_float4(-INFINITY, -INFINITY, -INFINITY, -INFINITY);
    float4 a0 = NEG, a1 = NEG;

    for (int h = hs; h < he; h += 2) {
        const float4* r0 = base + (size_t)(h * FM_W) * POS_F4;
        const float4* r1 = base + (size_t)(min(h + 1, FM_H - 1) * FM_W) * POS_F4;
        bool row1 = (h + 1) < he;
        for (int i = 0; i < n; i += 2) {
            int w0 = ws + i;
            int w1 = min(ws + i + 1, we - 1);   // odd tail -> duplicate (idempotent)
            float4 v00 = __ldg(r0 + (size_t)w0 * POS_F4);
            float4 v01 = __ldg(r0 + (size_t)w1 * POS_F4);
            float4 v10 = __ldg(r1 + (size_t)w0 * POS_F4);
            float4 v11 = __ldg(r1 + (size_t)w1 * POS_F4);
            a0 = f4max(a0, v00);
            a0 = f4max(a0, v01);
            if (row1) { a1 = f4max(a1, v10); a1 = f4max(a1, v11); }
        }
    }
    float4 a = f4max(a0, a1);

    int c0 = lane * 4;
    s_res[(c0 + 0) * POOL + pw] = (a.x == -INFINITY) ? 0.0f : a.x;
    s_res[(c0 + 1) * POOL + pw] = (a.y == -INFINITY) ? 0.0f : a.y;
    s_res[(c0 + 2) * POOL + pw] = (a.z == -INFINITY) ? 0.0f : a.z;
    s_res[(c0 + 3) * POOL + pw] = (a.w == -INFINITY) ? 0.0f : a.w;
    __syncthreads();

    // Writeback: out[(r*256 + half*128 + cl)*49 + ph*7 + pw]
    float* obase = out + ((size_t)r * FM_C + half * 128) * NBINS + ph * POOL;
    #pragma unroll
    for (int k = 0; k < 4; ++k) {
        int i = tid + k * 224;      // 0..895
        if (i < 128 * POOL) {
            int cl  = i / POOL;
            int pwk = i - cl * POOL;
            obase[cl * NBINS + pwk] = s_res[i];
        }
    }
}

extern "C" void kernel_launch(void* const* d_in, const int* in_sizes, int n_in,
                              void* d_out, int out_size) {
    const float* fm   = (const float*)d_in[0];
    const float* rois = (const float*)d_in[1];
    float* out        = (float*)d_out;

    dim3 tg((FM_HW + 31) / 32, FM_C / 32, FM_B);  // (79, 8, 2)
    transpose_kernel<<<tg, dim3(8, 32)>>>(fm, rois);

    roi_pool_f4<<<R_ROIS * POOL * 2, 224>>>(out);
}

// round 14
// speedup vs baseline: 1.2092x; 1.2092x over previous
#include <cuda_runtime.h>
#include <math.h>

#define FM_B 2
#define FM_C 256
#define FM_H 50
#define FM_W 50
#define FM_HW (FM_H * FM_W)      // 2500
#define POOL 7
#define NBINS (POOL * POOL)      // 49
#define R_ROIS 256
#define POS_F4 (FM_C / 4)        // 64 float4 per spatial position

// Channel-last scratch: [B, H, W, C] = 5.12 MB
__device__ float d_fm_t[FM_B * FM_HW * FM_C];
// LPT permutation: roi indices sorted by descending area
__device__ int d_perm[R_ROIS];

// ---------------------------------------------------------------------------
// Kernel 1: transpose [B, C, HW] -> [B, HW, C], float4 both sides.
// Block (0,0,0) additionally LPT-sorts the ROIs by area into d_perm.
// ---------------------------------------------------------------------------
__global__ void __launch_bounds__(256) transpose_kernel(
        const float* __restrict__ fm, const float* __restrict__ rois) {
    __shared__ float tile[32][33];
    __shared__ unsigned skey[R_ROIS];
    int hw0 = blockIdx.x * 32;
    int c0  = blockIdx.y * 32;
    int b   = blockIdx.z;
    int tx = threadIdx.x;   // 0..7
    int ty = threadIdx.y;   // 0..31
    int tid = ty * 8 + tx;  // 0..255

    bool sorter = (blockIdx.x == 0 && blockIdx.y == 0 && blockIdx.z == 0);

    // --- transpose tile ---
    int hw = hw0 + tx * 4;
    const float* src = fm + ((size_t)b * FM_C + c0 + ty) * FM_HW + hw;
    if (hw + 3 < FM_HW) {
        float4 v = *reinterpret_cast<const float4*>(src);
        tile[ty][tx * 4 + 0] = v.x; tile[ty][tx * 4 + 1] = v.y;
        tile[ty][tx * 4 + 2] = v.z; tile[ty][tx * 4 + 3] = v.w;
    } else {
        #pragma unroll
        for (int k = 0; k < 4; ++k)
            if (hw + k < FM_HW) tile[ty][tx * 4 + k] = src[k];
    }

    if (sorter) {
        // key = area<<8 | r  (area <= 2500 -> fits easily)
        int r = tid;
        const float* roi = rois + r * 5;
        int x1 = (int)rintf(roi[1]);
        int y1 = (int)rintf(roi[2]);
        int x2 = (int)rintf(roi[3]);
        int y2 = (int)rintf(roi[4]);
        int roi_w = max(x2 - x1 + 1, 1);
        int roi_h = max(y2 - y1 + 1, 1);
        skey[tid] = ((unsigned)(roi_w * roi_h) << 8) | (unsigned)r;
    }
    __syncthreads();

    int hw2 = hw0 + ty;
    if (hw2 < FM_HW) {
        float4 v;
        v.x = tile[tx * 4 + 0][ty]; v.y = tile[tx * 4 + 1][ty];
        v.z = tile[tx * 4 + 2][ty]; v.w = tile[tx * 4 + 3][ty];
        *reinterpret_cast<float4*>(
            d_fm_t + ((size_t)b * FM_HW + hw2) * FM_C + c0 + tx * 4) = v;
    }

    if (sorter) {
        // bitonic sort, DESCENDING by key
        #pragma unroll
        for (int k = 2; k <= R_ROIS; k <<= 1) {
            for (int j = k >> 1; j > 0; j >>= 1) {
                int ixj = tid ^ j;
                if (ixj > tid) {
                    unsigned a = skey[tid], bb = skey[ixj];
                    bool up = ((tid & k) == 0);
                    if ((a < bb) == up) { skey[tid] = bb; skey[ixj] = a; }
                }
                __syncthreads();
            }
        }
        d_perm[tid] = (int)(skey[tid] & 0xFFu);
    }
}

__device__ __forceinline__ float4 f4max(float4 a, float4 v) {
    a.x = fmaxf(a.x, v.x); a.y = fmaxf(a.y, v.y);
    a.z = fmaxf(a.z, v.z); a.w = fmaxf(a.w, v.w);
    return a;
}

// ---------------------------------------------------------------------------
// Kernel 2 (round-11 best, + LPT roi permutation):
// block = (roi-slot, ph strip, channel half), 224 threads = 7 warps.
// Warp wid owns bin pw = wid. Lane = float4 of 4 channels (coalesced 512B).
// Clamped always-4-load steady state (duplicates idempotent, keep MLP=4).
// ---------------------------------------------------------------------------
__global__ void __launch_bounds__(224) roi_pool_f4(
        const float* __restrict__ rois, float* __restrict__ out) {
    __shared__ float s_res[128 * POOL];   // [c_local][pw]

    int bid   = blockIdx.x;
    int half  = bid & 1;
    int ph    = (bid >> 1) % POOL;
    int rslot = bid / (2 * POOL);
    int r     = __ldg(&d_perm[rslot]);
    int tid   = threadIdx.x;
    int wid   = tid >> 5;       // 0..6 == pw
    int lane  = tid & 31;

    // --- uniform ROI decode ---
    const float* roi = rois + r * 5;
    int b  = (int)roi[0];
    int x1 = (int)rintf(roi[1]);
    int y1 = (int)rintf(roi[2]);
    int x2 = (int)rintf(roi[3]);
    int y2 = (int)rintf(roi[4]);
    int roi_w = max(x2 - x1 + 1, 1);
    int roi_h = max(y2 - y1 + 1, 1);
    // Replicate XLA fast-math: x/7 -> x * fl(1/7)  (0x3E124925)
    const float RCP7 = __uint_as_float(0x3E124925u);
    float bin_w = __fmul_rn((float)roi_w, RCP7);
    float bin_h = __fmul_rn((float)roi_h, RCP7);

    int hs = min(max(y1 + (int)floorf(__fmul_rn((float)ph,       bin_h)), 0), FM_H);
    int he = min(max(y1 + (int)ceilf (__fmul_rn((float)(ph + 1), bin_h)), 0), FM_H);

    int pw = wid;
    int ws = min(max(x1 + (int)floorf(__fmul_rn((float)pw,       bin_w)), 0), FM_W);
    int we = min(max(x1 + (int)ceilf (__fmul_rn((float)(pw + 1), bin_w)), 0), FM_W);
    int n  = we - ws;

    const float4* base = reinterpret_cast<const float4*>(d_fm_t)
                       + (size_t)b * FM_HW * POS_F4 + half * 32 + lane;

    const float4 NEG = make_float4(-INFINITY, -INFINITY, -INFINITY, -INFINITY);
    float4 a0 = NEG, a1 = NEG;

    for (int h = hs; h < he; h += 2) {
        const float4* r0 = base + (size_t)(h * FM_W) * POS_F4;
        const float4* r1 = base + (size_t)(min(h + 1, FM_H - 1) * FM_W) * POS_F4;
        bool row1 = (h + 1) < he;
        for (int i = 0; i < n; i += 2) {
            int w0 = ws + i;
            int w1 = min(ws + i + 1, we - 1);   // odd tail -> duplicate (idempotent)
            float4 v00 = __ldg(r0 + (size_t)w0 * POS_F4);
            float4 v01 = __ldg(r0 + (size_t)w1 * POS_F4);
            float4 v10 = __ldg(r1 + (size_t)w0 * POS_F4);
            float4 v11 = __ldg(r1 + (size_t)w1 * POS_F4);
            a0 = f4max(a0, v00);
            a0 = f4max(a0, v01);
            if (row1) { a1 = f4max(a1, v10); a1 = f4max(a1, v11); }
        }
    }
    float4 a = f4max(a0, a1);

    int c0 = lane * 4;
    s_res[(c0 + 0) * POOL + pw] = (a.x == -INFINITY) ? 0.0f : a.x;
    s_res[(c0 + 1) * POOL + pw] = (a.y == -INFINITY) ? 0.0f : a.y;
    s_res[(c0 + 2) * POOL + pw] = (a.z == -INFINITY) ? 0.0f : a.z;
    s_res[(c0 + 3) * POOL + pw] = (a.w == -INFINITY) ? 0.0f : a.w;
    __syncthreads();

    // Writeback: out[(r*256 + half*128 + cl)*49 + ph*7 + pw]
    float* obase = out + ((size_t)r * FM_C + half * 128) * NBINS + ph * POOL;
    #pragma unroll
    for (int k = 0; k < 4; ++k) {
        int i = tid + k * 224;      // 0..895
        if (i < 128 * POOL) {
            int cl  = i / POOL;
            int pwk = i - cl * POOL;
            obase[cl * NBINS + pwk] = s_res[i];
        }
    }
}

extern "C" void kernel_launch(void* const* d_in, const int* in_sizes, int n_in,
                              void* d_out, int out_size) {
    const float* fm   = (const float*)d_in[0];
    const float* rois = (const float*)d_in[1];
    float* out        = (float*)d_out;

    dim3 tg((FM_HW + 31) / 32, FM_C / 32, FM_B);  // (79, 8, 2)
    transpose_kernel<<<tg, dim3(8, 32)>>>(fm, rois);

    roi_pool_f4<<<R_ROIS * POOL * 2, 224>>>(rois, out);
}